// round 13
// baseline (speedup 1.0000x reference)
#include <cuda_runtime.h>
#include <math.h>

#define NQ 11
#define NL 3
#define SDIM 2048          // 2^NQ
#define BB 8
#define AA 96
#define NSTATE (BB*AA)     // 768
#define FDIM 64
#define NG (NL*NQ)         // 33 rotation gates
#define NE (NL*(NQ-1))     // 30 CNOT gates

// Device scratch (no cudaMalloc allowed). Zero at module load; the tail CTA
// re-zeroes g_R and resets g_done each launch, so every replay starts clean.
__device__ float g_R[BB * SDIM];                 // 64 KB pooled real amplitudes
__device__ int   g_done;                         // completed k1-CTA counter

// --- shared memory: UNION between k1 CTAs and the tail CTA ---------------
// UBUF (4352 floats = 17KB): k1 -> double-buffered transpose xbuf[2][2048]
//                            tail -> weight chunk / partial-sum buffer
// EXTRA (3400 floats = 13.6KB): k1 -> gate tables; tail -> activations/tables
#define UBN 4352
#define EXN 3400
// k1 EXTRA offsets
#define EX_HBUF 0
#define EX_F    64
#define EX_SCC  80
#define EX_SCS  180
#define EX_MG   280     // 33*4
#define EX_PENT 412
// tail EXTRA offsets
#define EX_H1S  0       // 8*256
#define EX_H2S  2048    // 8*128
#define EX_REP  3072    // 8*22
#define EX_PHC  3248    // 11
#define EX_PHS  3260    // 11
#define EX_QC   3272    // 64
#define EX_QS   3336    // 64

__global__ void __launch_bounds__(256, 6) qgnn_fused(
    const float* __restrict__ nf,   // [768,64]
    const float* __restrict__ W1,   // [64,100]
    const float* __restrict__ b1,   // [64]
    const float* __restrict__ W2,   // [11,64]
    const float* __restrict__ b2,   // [11]
    const float* __restrict__ rot,  // [3,11,3] flat
    const float* __restrict__ ent,  // [3,10]
    const float* __restrict__ pw,   // [11]
    const float* __restrict__ msg,  // [3,11,3]
    const float* __restrict__ Wo1, const float* __restrict__ bo1,
    const float* __restrict__ Wo2, const float* __restrict__ bo2,
    const float* __restrict__ Wo3, const float* __restrict__ bo3,
    float* __restrict__ out)        // [8,64]
{
    __shared__ float UBUF[UBN];
    __shared__ float EXTRA[EXN];
    const int tid  = threadIdx.x;
    const int lane = tid & 31;

    if (blockIdx.x < NSTATE) {
        // ================== k1: statevector CTA (see R9-R12) ==================
        const int n = blockIdx.x;
        float* hbuf = EXTRA + EX_HBUF;
        float* f    = EXTRA + EX_F;
        float* scc  = EXTRA + EX_SCC;
        float* scs  = EXTRA + EX_SCS;
        float* Mg   = EXTRA + EX_MG;    // [g*4 + i]
        float* pent = EXTRA + EX_PENT;

        const float* x = nf + n * FDIM;
        if (tid < 64) {
            float acc = b1[tid];
            const float* w = W1 + tid * 100;
            #pragma unroll 8
            for (int k = 0; k < 64; k++) acc = fmaf(x[k], w[k], acc);
            hbuf[tid] = fmaxf(acc, 0.f);
        }
        __syncthreads();

        if (tid < NQ) {
            float acc = b2[tid];
            const float* w = W2 + tid * 64;
            #pragma unroll 8
            for (int k = 0; k < 64; k++) acc = fmaf(hbuf[k], w[k], acc);
            f[tid] = tanhf(acc);
        }
        __syncthreads();

        if (tid < NG * 3) {
            const int g = tid / 3;
            const int q = g % NQ;
            float s_, c_;
            __sincosf(0.5f * rot[tid] * f[q], &s_, &c_);
            scc[tid] = c_; scs[tid] = s_;
        }
        __syncthreads();

        if (tid < NG) {
            const float cx = scc[3*tid+0], sx = scs[3*tid+0];
            const float cy = scc[3*tid+1], sy = scs[3*tid+1];
            const float cz = scc[3*tid+2], sz = scs[3*tid+2];
            Mg[tid*4+0] =  cx * cy * cz;
            Mg[tid*4+1] = -sx * sy * sz;
            Mg[tid*4+2] =  sx * sy * cz;
            Mg[tid*4+3] =  cx * cy * sz;
        } else if (tid >= 64 && tid < 64 + NE) {
            const int e = tid - 64;
            pent[e] = 1.f / (1.f + __expf(-ent[e]));
        }
        __syncthreads();

        const int wbits = (tid >> 5) & 7;
        const int tbase = (wbits << 8) | lane;

        // layer-0 rotations analytic (product state from |0>), LAYOUT B
        float r[8];
        {
            float laneP = 1.f;
            #pragma unroll
            for (int q = 0; q < 5; q++) laneP *= ((lane >> q) & 1) ? Mg[q*4+2] : Mg[q*4+0];
            float wP = 1.f;
            #pragma unroll
            for (int j = 0; j < 3; j++) wP *= ((wbits >> j) & 1) ? Mg[(8+j)*4+2] : Mg[(8+j)*4+0];
            const float lw = laneP * wP;
            #pragma unroll
            for (int k = 0; k < 8; k++) {
                float v = lw;
                #pragma unroll
                for (int j = 0; j < 3; j++) v *= ((k >> j) & 1) ? Mg[(5+j)*4+2] : Mg[(5+j)*4+0];
                r[k] = v;
            }
        }

        for (int l = 0; l < NL; l++) {
            if (l > 0) {
                // rotations lane qubits 0..4 : shfl
                #pragma unroll
                for (int q = 0; q < 5; q++) {
                    const int g = l * NQ + q;
                    const float M00 = Mg[g*4+0], M01 = Mg[g*4+1];
                    const float M10 = Mg[g*4+2], M11 = Mg[g*4+3];
                    const int m = 1 << q;
                    const bool h = (lane & m) != 0;
                    const float co = h ? M11 : M00;
                    const float ct = h ? M10 : M01;
                    #pragma unroll
                    for (int k = 0; k < 8; k++) {
                        const float o = __shfl_xor_sync(0xffffffffu, r[k], m);
                        r[k] = fmaf(co, r[k], ct * o);
                    }
                }
                // rotations reg qubits 8,9,10 : FMA
                #pragma unroll
                for (int j = 0; j < 3; j++) {
                    const int g = l * NQ + 8 + j;
                    const float M00 = Mg[g*4+0], M01 = Mg[g*4+1];
                    const float M10 = Mg[g*4+2], M11 = Mg[g*4+3];
                    #pragma unroll
                    for (int k = 0; k < 8; k++) {
                        if (!((k >> j) & 1)) {
                            const int k2 = k | (1 << j);
                            const float a = r[k], b = r[k2];
                            r[k]  = fmaf(M00, a, M01 * b);
                            r[k2] = fmaf(M10, a, M11 * b);
                        }
                    }
                }
                // TRANSPOSE A->B
                {
                    float* buf = UBUF;               // xbuf[0]
                    #pragma unroll
                    for (int k = 0; k < 8; k++) buf[k * 256 + tid] = r[k];
                    __syncthreads();
                    #pragma unroll
                    for (int k = 0; k < 8; k++) r[k] = buf[tbase + (k << 5)];
                }
                // rotations qubits 5,6,7 (reg bits in B) : FMA
                #pragma unroll
                for (int j = 0; j < 3; j++) {
                    const int g = l * NQ + 5 + j;
                    const float M00 = Mg[g*4+0], M01 = Mg[g*4+1];
                    const float M10 = Mg[g*4+2], M11 = Mg[g*4+3];
                    #pragma unroll
                    for (int k = 0; k < 8; k++) {
                        if (!((k >> j) & 1)) {
                            const int k2 = k | (1 << j);
                            const float a = r[k], b = r[k2];
                            r[k]  = fmaf(M00, a, M01 * b);
                            r[k2] = fmaf(M10, a, M11 * b);
                        }
                    }
                }
            }
            // CNOT chain q = 0..9 (LAYOUT B)
            #pragma unroll
            for (int q = 0; q < 4; q++) {
                const float p = pent[l * (NQ - 1) + q];
                const int m2 = 2 << q;
                const bool c = (lane & (1 << q)) != 0;
                #pragma unroll
                for (int k = 0; k < 8; k++) {
                    const float o = __shfl_xor_sync(0xffffffffu, r[k], m2);
                    const float mixed = fmaf(p, o - r[k], r[k]);
                    r[k] = c ? mixed : r[k];
                }
            }
            {   // q = 4
                const float p = pent[l * (NQ - 1) + 4];
                if (lane & 16) {
                    #pragma unroll
                    for (int k = 0; k < 8; k += 2) {
                        const float a = r[k], b = r[k + 1];
                        r[k]     = fmaf(p, b - a, a);
                        r[k + 1] = fmaf(p, a - b, b);
                    }
                }
            }
            {   // q = 5
                const float p = pent[l * (NQ - 1) + 5];
                { const float a = r[1], b = r[3]; r[1] = fmaf(p, b - a, a); r[3] = fmaf(p, a - b, b); }
                { const float a = r[5], b = r[7]; r[5] = fmaf(p, b - a, a); r[7] = fmaf(p, a - b, b); }
            }
            {   // q = 6
                const float p = pent[l * (NQ - 1) + 6];
                { const float a = r[2], b = r[6]; r[2] = fmaf(p, b - a, a); r[6] = fmaf(p, a - b, b); }
                { const float a = r[3], b = r[7]; r[3] = fmaf(p, b - a, a); r[7] = fmaf(p, a - b, b); }
            }
            // TRANSPOSE B->A
            {
                float* buf = UBUF + 2048;            // xbuf[1]
                #pragma unroll
                for (int k = 0; k < 8; k++) buf[k * 256 + tid] = r[k];
                __syncthreads();
                #pragma unroll
                for (int k = 0; k < 8; k++) r[k] = buf[tbase + (k << 5)];
            }
            {   // q = 7
                const float p = pent[l * (NQ - 1) + 7];
                if (tid & 128) {
                    #pragma unroll
                    for (int k = 0; k < 8; k += 2) {
                        const float a = r[k], b = r[k + 1];
                        r[k]     = fmaf(p, b - a, a);
                        r[k + 1] = fmaf(p, a - b, b);
                    }
                }
            }
            {   // q = 8
                const float p = pent[l * (NQ - 1) + 8];
                { const float a = r[1], b = r[3]; r[1] = fmaf(p, b - a, a); r[3] = fmaf(p, a - b, b); }
                { const float a = r[5], b = r[7]; r[5] = fmaf(p, b - a, a); r[7] = fmaf(p, a - b, b); }
            }
            {   // q = 9
                const float p = pent[l * (NQ - 1) + 9];
                { const float a = r[2], b = r[6]; r[2] = fmaf(p, b - a, a); r[6] = fmaf(p, a - b, b); }
                { const float a = r[3], b = r[7]; r[3] = fmaf(p, b - a, a); r[7] = fmaf(p, a - b, b); }
            }
        }

        // epilogue: pool-weighted REDG accumulate, then publish
        const float wa = 1.f / (1.f + __expf(-pw[(n % AA) % NQ]));
        float* Rb = g_R + (size_t)(n / AA) * SDIM;
        #pragma unroll
        for (int k = 0; k < 8; k++)
            atomicAdd(&Rb[k * 256 + tid], r[k] * wa);
        __threadfence();                 // each thread publishes its atomics
        __syncthreads();
        if (tid == 0) atomicAdd(&g_done, 1);
        return;
    }

    // ===================== TAIL CTA: pooling + MLP =====================
    {
        float* h1s = EXTRA + EX_H1S;     // [b*256+k]
        float* h2s = EXTRA + EX_H2S;     // [b*128+o]
        float* rep = EXTRA + EX_REP;     // [b*22+k]
        float* phc = EXTRA + EX_PHC;
        float* phs = EXTRA + EX_PHS;
        float* qc  = EXTRA + EX_QC;      // phasor table for state bits 5..10
        float* qs  = EXTRA + EX_QS;
        const int warp = tid >> 5;

        // ---- pre-wait work (overlaps with k1 CTAs running) ----
        if (tid < NQ) {
            float t = 0.f;
            for (int l = 0; l < NL; l++)
                for (int c = 0; c < 3; c++)
                    t += msg[(l * NQ + tid) * 3 + c];
            float s_, c_;
            sincosf(t, &s_, &c_);
            phc[tid] = c_; phs[tid] = s_;
        }
        __syncthreads();
        if (tid < 64) {                  // table over state bits 5..10
            float c = 1.f, s = 0.f;
            #pragma unroll
            for (int jb = 0; jb < 6; jb++) {
                if ((tid >> jb) & 1) {
                    const float pc = phc[5 + jb], ps = phs[5 + jb];
                    const float nc = c * pc - s * ps;
                    s = c * ps + s * pc;
                    c = nc;
                }
            }
            qc[tid] = c; qs[tid] = s;
        }
        float Pc = 1.f, Ps = 0.f;        // per-thread phasor over bits 0..4
        #pragma unroll
        for (int q = 0; q < 5; q++) {
            if ((lane >> q) & 1) {
                const float pc = phc[q], ps = phs[q];
                const float nc = Pc * pc - Ps * ps;
                Ps = Pc * ps + Ps * pc;
                Pc = nc;
            }
        }
        // stage Wo1 chunk 0 (outputs 0..127) while k1 still runs
        for (int i = tid; i < 128 * 22; i += 256) UBUF[i] = Wo1[i];
        __syncthreads();

        // ---- spin-wait for all 768 state CTAs ----
        if (tid == 0) {
            volatile int* p = &g_done;
            while (*p < NSTATE) __nanosleep(64);
            __threadfence();             // acquire
        }
        __syncthreads();

        // ---- stats: warp b handles batch b; 64 s-values per lane ----
        {
            const int b = warp;
            float s2 = 0.f, sc = 0.f, ss = 0.f;
            float* Rb = g_R + b * SDIM;
            #pragma unroll 8
            for (int j = 0; j < 64; j++) {
                const int s = (j << 5) | lane;
                const float R = Rb[s];
                Rb[s] = 0.f;             // re-zero for next replay
                const float cp = Pc * qc[j] - Ps * qs[j];   // j uniform/warp
                const float sp = Pc * qs[j] + Ps * qc[j];
                s2 = fmaf(R, R, s2);
                sc = fmaf(R, cp, sc);
                ss = fmaf(R, sp, ss);
            }
            #pragma unroll
            for (int o = 16; o > 0; o >>= 1) {
                s2 += __shfl_xor_sync(0xffffffffu, s2, o);
                sc += __shfl_xor_sync(0xffffffffu, sc, o);
                ss += __shfl_xor_sync(0xffffffffu, ss, o);
            }
            if (lane == 0) {
                const float inv = 1.f / (fmaxf(sqrtf(s2), 1e-12f) * (float)SDIM);
                const float rm = sc * inv, im = ss * inv;
                for (int q = 0; q < NQ; q++) {
                    rep[b * 22 + q]      = rm;
                    rep[b * 22 + NQ + q] = im;
                }
            }
        }
        __syncthreads();

        // ---- layer 1: two chunks of 128 outputs (chunk 0 pre-staged) ----
        for (int c = 0; c < 2; c++) {
            if (c) {
                __syncthreads();
                for (int i = tid; i < 128 * 22; i += 256) UBUF[i] = Wo1[128 * 22 + i];
                __syncthreads();
            }
            if (tid < 128) {
                const int o = c * 128 + tid;
                float acc[BB];
                const float bias = bo1[o];
                #pragma unroll
                for (int b = 0; b < BB; b++) acc[b] = bias;
                #pragma unroll
                for (int k = 0; k < 22; k++) {
                    const float w = UBUF[tid * 22 + k];
                    #pragma unroll
                    for (int b = 0; b < BB; b++) acc[b] = fmaf(w, rep[b * 22 + k], acc[b]);
                }
                #pragma unroll
                for (int b = 0; b < BB; b++) h1s[b * 256 + o] = fmaxf(acc[b], 0.f);
            }
        }

        // ---- layer 2: 8 chunks of 32 k; thread (o = tid&127, sub = tid>>7) ----
        {
            const int o2  = tid & 127;
            const int sub = tid >> 7;
            float acc2[BB];
            #pragma unroll
            for (int b = 0; b < BB; b++) acc2[b] = 0.f;
            for (int c = 0; c < 8; c++) {
                __syncthreads();
                for (int i = tid; i < 128 * 32; i += 256) {
                    const int oo = i >> 5, kk = i & 31;
                    UBUF[oo * 33 + kk] = Wo2[oo * 256 + c * 32 + kk];
                }
                __syncthreads();
                #pragma unroll
                for (int kk = 0; kk < 16; kk++) {
                    const int kl = sub * 16 + kk;        // uniform per warp
                    const float w = UBUF[o2 * 33 + kl];
                    const int kg = c * 32 + kl;
                    #pragma unroll
                    for (int b = 0; b < BB; b++)
                        acc2[b] = fmaf(w, h1s[b * 256 + kg], acc2[b]);
                }
            }
            __syncthreads();
            #pragma unroll
            for (int b = 0; b < BB; b++) UBUF[(sub * 128 + o2) * 8 + b] = acc2[b];
        }
        __syncthreads();
        if (tid < 128) {
            for (int b = 0; b < BB; b++) {
                const float v = bo2[tid]
                              + UBUF[tid * 8 + b]
                              + UBUF[(128 + tid) * 8 + b];
                h2s[b * 128 + tid] = fmaxf(v, 0.f);
            }
        }

        // ---- layer 3: 2 chunks of 64 k; thread (o = tid&63, g = tid>>6) ----
        {
            const int o3 = tid & 63;
            const int g3 = tid >> 6;                     // 0..3, uniform/warp
            float acc3[BB];
            #pragma unroll
            for (int b = 0; b < BB; b++) acc3[b] = 0.f;
            for (int c = 0; c < 2; c++) {
                __syncthreads();
                for (int i = tid; i < 64 * 64; i += 256) {
                    const int oo = i >> 6, kk = i & 63;
                    UBUF[oo * 65 + kk] = Wo3[oo * 128 + c * 64 + kk];
                }
                __syncthreads();
                #pragma unroll
                for (int kk = 0; kk < 16; kk++) {
                    const int kl = g3 * 16 + kk;         // uniform per warp
                    const float w = UBUF[o3 * 65 + kl];
                    const int kg = c * 64 + kl;
                    #pragma unroll
                    for (int b = 0; b < BB; b++)
                        acc3[b] = fmaf(w, h2s[b * 128 + kg], acc3[b]);
                }
            }
            __syncthreads();
            #pragma unroll
            for (int b = 0; b < BB; b++) UBUF[(g3 * 64 + o3) * 8 + b] = acc3[b];
        }
        __syncthreads();
        {   // out: 512 values, 2 per thread
            const int o  = tid & 63;
            const int bh = tid >> 6;                     // 0..3
            #pragma unroll
            for (int t = 0; t < 2; t++) {
                const int b = bh * 2 + t;
                float v = bo3[o];
                #pragma unroll
                for (int g = 0; g < 4; g++) v += UBUF[(g * 64 + o) * 8 + b];
                out[b * 64 + o] = v;
            }
        }
        __syncthreads();
        if (tid == 0) g_done = 0;        // reset for next graph replay
    }
}

// ---------------------------------------------------------------------------
extern "C" void kernel_launch(void* const* d_in, const int* in_sizes, int n_in,
                              void* d_out, int out_size)
{
    const float* nf   = (const float*)d_in[0];
    // d_in[1] = edge_indices (int32) — unused by the math
    const float* W1   = (const float*)d_in[2];
    const float* b1   = (const float*)d_in[3];
    const float* W2   = (const float*)d_in[4];
    const float* b2   = (const float*)d_in[5];
    const float* rot  = (const float*)d_in[6];
    const float* ent  = (const float*)d_in[7];
    const float* msg  = (const float*)d_in[8];
    const float* pw   = (const float*)d_in[9];
    const float* Wo1  = (const float*)d_in[10];
    const float* bo1  = (const float*)d_in[11];
    const float* Wo2  = (const float*)d_in[12];
    const float* bo2  = (const float*)d_in[13];
    const float* Wo3  = (const float*)d_in[14];
    const float* bo3  = (const float*)d_in[15];
    float* out = (float*)d_out;

    qgnn_fused<<<NSTATE + 1, 256>>>(nf, W1, b1, W2, b2, rot, ent, pw,
                                    msg, Wo1, bo1, Wo2, bo2, Wo3, bo3, out);
}

// round 17
// speedup vs baseline: 1.4590x; 1.4590x over previous
#include <cuda_runtime.h>
#include <math.h>

#define NQ 11
#define NL 3
#define SDIM 2048          // 2^NQ
#define BB 8
#define AA 96
#define NSTATE (BB*AA)     // 768
#define FDIM 64
#define NG (NL*NQ)         // 33 rotation gates
#define NE (NL*(NQ-1))     // 30 CNOT gates

// Accumulation buffer (no cudaMalloc allowed). Zero-initialized at module load;
// k23 re-zeroes it after reading, so every graph replay sees R == 0 on entry.
__device__ float g_R[BB * SDIM];                 // 64 KB pooled real amplitudes

// ---------------------------------------------------------------------------
// Kernel 1: one CTA per state n. Register-resident statevector (R9-R12 form).
// ---------------------------------------------------------------------------
__global__ __launch_bounds__(256) void k1_state(
    const float* __restrict__ nf,   // [768,64]
    const float* __restrict__ W1,   // [64,100]
    const float* __restrict__ b1,   // [64]
    const float* __restrict__ W2,   // [11,64]
    const float* __restrict__ b2,   // [11]
    const float* __restrict__ rot,  // [3,11,3] flat
    const float* __restrict__ ent,  // [3,10]
    const float* __restrict__ pw)   // [11]
{
    __shared__ float xbuf[2][SDIM];          // 16KB double-buffered transpose
    __shared__ float hbuf[64];
    __shared__ float f[NQ];
    __shared__ float scc[NG * 3], scs[NG * 3];
    __shared__ float Mg[NG][4];
    __shared__ float pent[NE];
    const int n    = blockIdx.x;
    const int tid  = threadIdx.x;
    const int lane = tid & 31;

    // --- feature preprocessor: h = relu(x @ W1[:, :64]^T + b1) ---
    const float* x = nf + n * FDIM;
    if (tid < 64) {
        float acc = b1[tid];
        const float* w = W1 + tid * 100;
        #pragma unroll 8
        for (int k = 0; k < 64; k++) acc = fmaf(x[k], w[k], acc);
        hbuf[tid] = fmaxf(acc, 0.f);
    }
    __syncthreads();

    if (tid < NQ) {
        float acc = b2[tid];
        const float* w = W2 + tid * 64;
        #pragma unroll 8
        for (int k = 0; k < 64; k++) acc = fmaf(hbuf[k], w[k], acc);
        f[tid] = tanhf(acc);
    }
    __syncthreads();

    if (tid < NG * 3) {
        const int g = tid / 3;
        const int q = g % NQ;
        float s_, c_;
        __sincosf(0.5f * rot[tid] * f[q], &s_, &c_);
        scc[tid] = c_; scs[tid] = s_;
    }
    __syncthreads();

    if (tid < NG) {
        const float cx = scc[3*tid+0], sx = scs[3*tid+0];
        const float cy = scc[3*tid+1], sy = scs[3*tid+1];
        const float cz = scc[3*tid+2], sz = scs[3*tid+2];
        Mg[tid][0] =  cx * cy * cz;
        Mg[tid][1] = -sx * sy * sz;
        Mg[tid][2] =  sx * sy * cz;
        Mg[tid][3] =  cx * cy * sz;
    } else if (tid >= 64 && tid < 64 + NE) {
        const int e = tid - 64;
        pent[e] = 1.f / (1.f + __expf(-ent[e]));
    }
    __syncthreads();

    const int wbits = (tid >> 5) & 7;
    const int tbase = (wbits << 8) | lane;

    // layer-0 rotations analytic (product state from |0>), LAYOUT B
    float r[8];
    {
        float laneP = 1.f;
        #pragma unroll
        for (int q = 0; q < 5; q++) laneP *= ((lane >> q) & 1) ? Mg[q][2] : Mg[q][0];
        float wP = 1.f;
        #pragma unroll
        for (int j = 0; j < 3; j++) wP *= ((wbits >> j) & 1) ? Mg[8 + j][2] : Mg[8 + j][0];
        const float lw = laneP * wP;
        #pragma unroll
        for (int k = 0; k < 8; k++) {
            float v = lw;
            #pragma unroll
            for (int j = 0; j < 3; j++) v *= ((k >> j) & 1) ? Mg[5 + j][2] : Mg[5 + j][0];
            r[k] = v;
        }
    }

    for (int l = 0; l < NL; l++) {
        if (l > 0) {
            #pragma unroll
            for (int q = 0; q < 5; q++) {
                const int g = l * NQ + q;
                const float M00 = Mg[g][0], M01 = Mg[g][1];
                const float M10 = Mg[g][2], M11 = Mg[g][3];
                const int m = 1 << q;
                const bool h = (lane & m) != 0;
                const float co = h ? M11 : M00;
                const float ct = h ? M10 : M01;
                #pragma unroll
                for (int k = 0; k < 8; k++) {
                    const float o = __shfl_xor_sync(0xffffffffu, r[k], m);
                    r[k] = fmaf(co, r[k], ct * o);
                }
            }
            #pragma unroll
            for (int j = 0; j < 3; j++) {
                const int g = l * NQ + 8 + j;
                const float M00 = Mg[g][0], M01 = Mg[g][1];
                const float M10 = Mg[g][2], M11 = Mg[g][3];
                #pragma unroll
                for (int k = 0; k < 8; k++) {
                    if (!((k >> j) & 1)) {
                        const int k2 = k | (1 << j);
                        const float a = r[k], b = r[k2];
                        r[k]  = fmaf(M00, a, M01 * b);
                        r[k2] = fmaf(M10, a, M11 * b);
                    }
                }
            }
            {   // TRANSPOSE A->B
                float* buf = xbuf[0];
                #pragma unroll
                for (int k = 0; k < 8; k++) buf[k * 256 + tid] = r[k];
                __syncthreads();
                #pragma unroll
                for (int k = 0; k < 8; k++) r[k] = buf[tbase + (k << 5)];
            }
            #pragma unroll
            for (int j = 0; j < 3; j++) {
                const int g = l * NQ + 5 + j;
                const float M00 = Mg[g][0], M01 = Mg[g][1];
                const float M10 = Mg[g][2], M11 = Mg[g][3];
                #pragma unroll
                for (int k = 0; k < 8; k++) {
                    if (!((k >> j) & 1)) {
                        const int k2 = k | (1 << j);
                        const float a = r[k], b = r[k2];
                        r[k]  = fmaf(M00, a, M01 * b);
                        r[k2] = fmaf(M10, a, M11 * b);
                    }
                }
            }
        }
        // CNOT chain q = 0..9 (LAYOUT B)
        #pragma unroll
        for (int q = 0; q < 4; q++) {
            const float p = pent[l * (NQ - 1) + q];
            const int m2 = 2 << q;
            const bool c = (lane & (1 << q)) != 0;
            #pragma unroll
            for (int k = 0; k < 8; k++) {
                const float o = __shfl_xor_sync(0xffffffffu, r[k], m2);
                const float mixed = fmaf(p, o - r[k], r[k]);
                r[k] = c ? mixed : r[k];
            }
        }
        {   // q = 4
            const float p = pent[l * (NQ - 1) + 4];
            if (lane & 16) {
                #pragma unroll
                for (int k = 0; k < 8; k += 2) {
                    const float a = r[k], b = r[k + 1];
                    r[k]     = fmaf(p, b - a, a);
                    r[k + 1] = fmaf(p, a - b, b);
                }
            }
        }
        {   // q = 5
            const float p = pent[l * (NQ - 1) + 5];
            { const float a = r[1], b = r[3]; r[1] = fmaf(p, b - a, a); r[3] = fmaf(p, a - b, b); }
            { const float a = r[5], b = r[7]; r[5] = fmaf(p, b - a, a); r[7] = fmaf(p, a - b, b); }
        }
        {   // q = 6
            const float p = pent[l * (NQ - 1) + 6];
            { const float a = r[2], b = r[6]; r[2] = fmaf(p, b - a, a); r[6] = fmaf(p, a - b, b); }
            { const float a = r[3], b = r[7]; r[3] = fmaf(p, b - a, a); r[7] = fmaf(p, a - b, b); }
        }
        {   // TRANSPOSE B->A
            float* buf = xbuf[1];
            #pragma unroll
            for (int k = 0; k < 8; k++) buf[k * 256 + tid] = r[k];
            __syncthreads();
            #pragma unroll
            for (int k = 0; k < 8; k++) r[k] = buf[tbase + (k << 5)];
        }
        {   // q = 7
            const float p = pent[l * (NQ - 1) + 7];
            if (tid & 128) {
                #pragma unroll
                for (int k = 0; k < 8; k += 2) {
                    const float a = r[k], b = r[k + 1];
                    r[k]     = fmaf(p, b - a, a);
                    r[k + 1] = fmaf(p, a - b, b);
                }
            }
        }
        {   // q = 8
            const float p = pent[l * (NQ - 1) + 8];
            { const float a = r[1], b = r[3]; r[1] = fmaf(p, b - a, a); r[3] = fmaf(p, a - b, b); }
            { const float a = r[5], b = r[7]; r[5] = fmaf(p, b - a, a); r[7] = fmaf(p, a - b, b); }
        }
        {   // q = 9
            const float p = pent[l * (NQ - 1) + 9];
            { const float a = r[2], b = r[6]; r[2] = fmaf(p, b - a, a); r[6] = fmaf(p, a - b, b); }
            { const float a = r[3], b = r[7]; r[3] = fmaf(p, b - a, a); r[7] = fmaf(p, a - b, b); }
        }
    }

    // accumulate pool-weighted amps into R[b][s] (coalesced REDG)
    const float wa = 1.f / (1.f + __expf(-pw[(n % AA) % NQ]));
    float* Rb = g_R + (size_t)(n / AA) * SDIM;
    #pragma unroll
    for (int k = 0; k < 8; k++)
        atomicAdd(&Rb[k * 256 + tid], r[k] * wa);
}

// ---------------------------------------------------------------------------
// Kernel 2: ONE CTA PER BATCH (8 CTAs, 256 threads). Per CTA:
//   stats over R[b] (phasor factorization, no per-s sincosf),
//   rank-1 layer 1 (rep = [rm x11, im x11] => row-half-sums A,B of Wo1),
//   layers 2/3 as warp-per-output-row dots straight from global (each weight
//   used once -> no staging), 5-shfl butterfly reduce per row.
// ---------------------------------------------------------------------------
__global__ __launch_bounds__(256) void k23_batch(
    const float* __restrict__ msg,                                  // [3,11,3]
    const float* __restrict__ Wo1, const float* __restrict__ bo1,   // [256,22],[256]
    const float* __restrict__ Wo2, const float* __restrict__ bo2,   // [128,256],[128]
    const float* __restrict__ Wo3, const float* __restrict__ bo3,   // [64,128],[64]
    float* __restrict__ out)                                        // [8,64]
{
    __shared__ __align__(16) float w1s[256 * 22];   // 22KB Wo1, FLAT row-major copy
    __shared__ __align__(16) float h1s[256];
    __shared__ __align__(16) float h2s[128];
    __shared__ float red[3][8];
    __shared__ float phc[NQ], phs[NQ];
    __shared__ float t8c[8], t8s[8];                // phasors for state bits 8..10
    __shared__ float rmim[2];
    const int b    = blockIdx.x;
    const int tid  = threadIdx.x;
    const int lane = tid & 31;
    const int warp = tid >> 5;                      // 0..7

    // --- 1. R loads first (latency overlaps everything below) ---
    float Rv[8];
    float* Rb = g_R + b * SDIM;
    #pragma unroll
    for (int j = 0; j < 8; j++) Rv[j] = Rb[j * 256 + tid];   // s = j*256 + tid
    #pragma unroll
    for (int j = 0; j < 8; j++) Rb[j * 256 + tid] = 0.f;     // re-zero for replay

    // --- 2. stage Wo1 flat (coalesced; layout stays row-major [o*22+k]) ---
    #pragma unroll
    for (int i = 0; i < 22; i++) w1s[i * 256 + tid] = Wo1[i * 256 + tid];
    if (tid < NQ) {
        float t = 0.f;
        for (int l = 0; l < NL; l++)
            for (int c = 0; c < 3; c++)
                t += msg[(l * NQ + tid) * 3 + c];
        float s_, c_;
        sincosf(t, &s_, &c_);
        phc[tid] = c_; phs[tid] = s_;
    }
    __syncthreads();

    // --- 3. phasor table bits 8..10 + per-thread phasor bits 0..7 ---
    if (tid < 8) {
        float c = 1.f, s = 0.f;
        #pragma unroll
        for (int jb = 0; jb < 3; jb++) {
            if ((tid >> jb) & 1) {
                const float pc = phc[8 + jb], ps = phs[8 + jb];
                const float nc = c * pc - s * ps;
                s = c * ps + s * pc;
                c = nc;
            }
        }
        t8c[tid] = c; t8s[tid] = s;
    }
    float Pc = 1.f, Ps = 0.f;
    #pragma unroll
    for (int q = 0; q < 8; q++) {
        if ((tid >> q) & 1) {
            const float pc = phc[q], ps = phs[q];
            const float nc = Pc * pc - Ps * ps;
            Ps = Pc * ps + Ps * pc;
            Pc = nc;
        }
    }
    // rank-1 layer-1 prep: row tid of Wo1 is w1s[tid*22 .. tid*22+21]
    //   A = sum over k=0..10, B = sum over k=11..21   (FIXED indexing)
    float Arow = 0.f, Brow = 0.f;
    {
        const float* wr = w1s + tid * 22;
        #pragma unroll
        for (int k = 0; k < 11; k++)  Arow += wr[k];
        #pragma unroll
        for (int k = 11; k < 22; k++) Brow += wr[k];
    }
    __syncthreads();   // t8 visible

    // --- 4. stats ---
    {
        float s2 = 0.f, sc = 0.f, ss = 0.f;
        #pragma unroll
        for (int j = 0; j < 8; j++) {
            const float R  = Rv[j];
            const float cp = Pc * t8c[j] - Ps * t8s[j];
            const float sp = Pc * t8s[j] + Ps * t8c[j];
            s2 = fmaf(R, R, s2);
            sc = fmaf(R, cp, sc);
            ss = fmaf(R, sp, ss);
        }
        #pragma unroll
        for (int o = 16; o > 0; o >>= 1) {
            s2 += __shfl_xor_sync(0xffffffffu, s2, o);
            sc += __shfl_xor_sync(0xffffffffu, sc, o);
            ss += __shfl_xor_sync(0xffffffffu, ss, o);
        }
        if (lane == 0) { red[0][warp] = s2; red[1][warp] = sc; red[2][warp] = ss; }
    }
    __syncthreads();
    if (tid == 0) {
        float s2 = 0.f, sc = 0.f, ss = 0.f;
        #pragma unroll
        for (int w = 0; w < 8; w++) { s2 += red[0][w]; sc += red[1][w]; ss += red[2][w]; }
        const float inv = 1.f / (fmaxf(sqrtf(s2), 1e-12f) * (float)SDIM);
        rmim[0] = sc * inv;
        rmim[1] = ss * inv;
    }
    __syncthreads();

    // --- 5. layer 1 (rank-1): h1[o] = relu(bo1 + rm*A + im*B), o = tid ---
    h1s[tid] = fmaxf(fmaf(rmim[0], Arow, fmaf(rmim[1], Brow, bo1[tid])), 0.f);
    __syncthreads();

    // --- 6. layer 2: warp w -> rows o = w*16..w*16+15, straight from global ---
    {
        float d[16];
        const float4* h1v = (const float4*)h1s;
        const float4 h0 = h1v[lane * 2], h1x = h1v[lane * 2 + 1];  // k = lane*8..+7
        #pragma unroll
        for (int rr = 0; rr < 16; rr++) {
            const int o = warp * 16 + rr;
            const float4* wr = (const float4*)(Wo2 + o * 256);
            const float4 a = wr[lane * 2], c = wr[lane * 2 + 1];
            d[rr] = a.x*h0.x + a.y*h0.y + a.z*h0.z + a.w*h0.w
                  + c.x*h1x.x + c.y*h1x.y + c.z*h1x.z + c.w*h1x.w;
        }
        #pragma unroll
        for (int rr = 0; rr < 16; rr++) {
            #pragma unroll
            for (int o2 = 16; o2 > 0; o2 >>= 1)
                d[rr] += __shfl_xor_sync(0xffffffffu, d[rr], o2);
        }
        #pragma unroll
        for (int rr = 0; rr < 16; rr++) {
            if (lane == rr) {
                const int o = warp * 16 + rr;
                h2s[o] = fmaxf(d[rr] + bo2[o], 0.f);
            }
        }
    }
    __syncthreads();

    // --- 7. layer 3: warp w -> rows o = w*8..w*8+7 ---
    {
        float d[8];
        const float4 h = ((const float4*)h2s)[lane];               // k = lane*4..+3
        #pragma unroll
        for (int rr = 0; rr < 8; rr++) {
            const int o = warp * 8 + rr;
            const float4 a = ((const float4*)(Wo3 + o * 128))[lane];
            d[rr] = a.x*h.x + a.y*h.y + a.z*h.z + a.w*h.w;
        }
        #pragma unroll
        for (int rr = 0; rr < 8; rr++) {
            #pragma unroll
            for (int o2 = 16; o2 > 0; o2 >>= 1)
                d[rr] += __shfl_xor_sync(0xffffffffu, d[rr], o2);
        }
        #pragma unroll
        for (int rr = 0; rr < 8; rr++) {
            if (lane == rr) {
                const int o = warp * 8 + rr;
                out[b * 64 + o] = d[rr] + bo3[o];
            }
        }
    }
}

// ---------------------------------------------------------------------------
extern "C" void kernel_launch(void* const* d_in, const int* in_sizes, int n_in,
                              void* d_out, int out_size)
{
    const float* nf   = (const float*)d_in[0];
    // d_in[1] = edge_indices (int32) — unused by the math
    const float* W1   = (const float*)d_in[2];
    const float* b1   = (const float*)d_in[3];
    const float* W2   = (const float*)d_in[4];
    const float* b2   = (const float*)d_in[5];
    const float* rot  = (const float*)d_in[6];
    const float* ent  = (const float*)d_in[7];
    const float* msg  = (const float*)d_in[8];
    const float* pw   = (const float*)d_in[9];
    const float* Wo1  = (const float*)d_in[10];
    const float* bo1  = (const float*)d_in[11];
    const float* Wo2  = (const float*)d_in[12];
    const float* bo2  = (const float*)d_in[13];
    const float* Wo3  = (const float*)d_in[14];
    const float* bo3  = (const float*)d_in[15];
    float* out = (float*)d_out;

    k1_state<<<NSTATE, 256>>>(nf, W1, b1, W2, b2, rot, ent, pw);
    k23_batch<<<BB, 256>>>(msg, Wo1, bo1, Wo2, bo2, Wo3, bo3, out);
}